// round 13
// baseline (speedup 1.0000x reference)
#include <cuda_runtime.h>
#include <cstdint>

// NAF layer: A = -0.5 * d^T (L L^T) d  ==  -0.5 * ||L^T d||^2
// L lower-triangular, packed row-major (tril order): (i,j) at i*(i+1)/2 + j.
// Diagonal entries exp(x)+eps, off-diagonal raw.
//
// R12 lesson: persistence at WPB=2 double-buffer halved warps/SM (12) and the
// consume phase became latency-bound. This version: persistent, WPB=4, ONE
// 8320B buffer per warp (24 warps/SM like R11), software-pipelined at chunk
// granularity with zero extra smem: after rows 0..31 are consumed, chunk A's
// region is dead, so next row's chunk A is cp.async'd into it immediately
// (WAR safe: LDS reads issue before the LDGSTS and complete in ~29cyc; the
// async smem write lands >=234cyc after issue). Grid = 6 x #SMs -> no wave
// tail, no oversubscription stragglers.
// One warp per batch row; lane l owns columns j=l and j=l+32.

#define NB_ACTIONS 64
#define NB_ELEMS   2080            // 520 float4 per row
#define EPSV       1e-7f
#define TRI(i) ((i) * ((i) + 1) / 2)
#define WPB    4                   // warps per block

// chunk boundaries in float4 units (floats: 0..527 | 528..1175 | 1176..2079)
#define F4_A   132                 // TRI(32)/4
#define F4_B   294                 // TRI(48)/4
#define F4_C   520                 // TRI(64)/4

#define CPA(dst, src) \
    asm volatile("cp.async.cg.shared.global [%0], [%1], 16;\n" \
                 :: "r"(dst), "l"(src))

__global__ __launch_bounds__(32 * WPB, 6)
void naf_kernel(const float* __restrict__ Lf,
                const float* __restrict__ mu,
                const float* __restrict__ a,
                float* __restrict__ out,
                int B)
{
    __shared__ float sbuf[WPB][NB_ELEMS];   // 33,280 B/block

    const int lane = threadIdx.x & 31;
    const int wl   = threadIdx.x >> 5;
    const int strd = gridDim.x * WPB;
    const int j1   = lane + 32;

    float* __restrict__ sw = sbuf[wl];
    const unsigned int sbase = (unsigned int)__cvta_generic_to_shared(sw);

    // ---- Prologue: chunk A of first row ----
    int row = blockIdx.x * WPB + wl;
    if (row < B) {
        const float4* __restrict__ src =
            (const float4*)(Lf + (size_t)row * NB_ELEMS);
        #pragma unroll
        for (int it = 0; it < 5; ++it) {
            const int idx = it * 32 + lane;
            if (idx < F4_A) CPA(sbase + idx * 16, src + idx);
        }
    }
    asm volatile("cp.async.commit_group;\n");          // pending: [A]

    for (; row < B; row += strd) {
        const float4* __restrict__ src =
            (const float4*)(Lf + (size_t)row * NB_ELEMS);

        // ---- Issue chunks B and C of the current row ----
        #pragma unroll
        for (int it = 0; it < 6; ++it) {
            const int idx = F4_A + it * 32 + lane;
            if (idx < F4_B) CPA(sbase + idx * 16, src + idx);
        }
        asm volatile("cp.async.commit_group;\n");      // pending: [A,B]
        #pragma unroll
        for (int it = 0; it < 8; ++it) {
            const int idx = F4_B + it * 32 + lane;
            if (idx < F4_C) CPA(sbase + idx * 16, src + idx);
        }
        asm volatile("cp.async.commit_group;\n");      // pending: [A,B,C]

        // d-vector loads in flight before the wait
        const size_t vb = (size_t)row * NB_ACTIONS;
        const float a0 = a[vb + lane], m0 = mu[vb + lane];
        const float a1 = a[vb + j1],   m1 = mu[vb + j1];

        // ---- Chunk A ready (issued one half-row earlier in steady state) ----
        asm volatile("cp.async.wait_group 2;\n" ::: "memory");
        __syncwarp();

        const float dlo = a0 - m0;     // d[lane]
        const float dhi = a1 - m1;     // d[lane+32]

        const float diagRaw0 = sw[TRI(lane) + lane];   // in chunk A

        float y0 = 0.0f;   // column j = lane
        float y1 = 0.0f;   // column j = lane + 32

        // Rows 0..31: y0 only; diagonal kept raw, corrected afterwards.
        #pragma unroll
        for (int i = 0; i < 32; ++i) {
            const float v  = sw[TRI(i) + lane];        // conflict-free LDS
            const float di = __shfl_sync(0xffffffffu, dlo, i);
            const float m  = (lane <= i) ? di : 0.0f;
            y0 = fmaf(v, m, y0);
        }

        // ---- Chunk A region is dead: prefetch NEXT row's chunk A into it ----
        {
            const int nrow = row + strd;
            if (nrow < B) {
                const float4* __restrict__ nsrc =
                    (const float4*)(Lf + (size_t)nrow * NB_ELEMS);
                #pragma unroll
                for (int it = 0; it < 5; ++it) {
                    const int idx = it * 32 + lane;
                    if (idx < F4_A) CPA(sbase + idx * 16, nsrc + idx);
                }
            }
            asm volatile("cp.async.commit_group;\n");  // pending: [B,C,A']
        }

        // ---- Chunk B ready: rows 32..47 ----
        asm volatile("cp.async.wait_group 2;\n" ::: "memory");
        __syncwarp();

        #pragma unroll
        for (int i = 32; i < 48; ++i) {
            const int t = TRI(i);
            const float vlo = sw[t + lane];
            const float vhi = sw[t + j1];
            const float di  = __shfl_sync(0xffffffffu, dhi, i - 32);
            y0 = fmaf(vlo, di, y0);
            const float m = (j1 <= i) ? di : 0.0f;
            y1 = fmaf(vhi, m, y1);
        }

        // ---- Chunk C ready: rows 48..63 ----
        asm volatile("cp.async.wait_group 1;\n" ::: "memory");
        __syncwarp();

        #pragma unroll
        for (int i = 48; i < 64; ++i) {
            const int t = TRI(i);
            const float vlo = sw[t + lane];
            const float vhi = sw[t + j1];
            const float di  = __shfl_sync(0xffffffffu, dhi, i - 32);
            y0 = fmaf(vlo, di, y0);
            const float m = (j1 <= i) ? di : 0.0f;
            y1 = fmaf(vhi, m, y1);
        }

        // Diagonal correction: raw*d added in loops; want (exp(raw)+eps)*d.
        const float diagRaw1 = sw[TRI(j1) + j1];       // chunk B or C (both ready)
        y0 = fmaf(expf(diagRaw0) + EPSV - diagRaw0, dlo, y0);
        y1 = fmaf(expf(diagRaw1) + EPSV - diagRaw1, dhi, y1);

        // quad = sum_j y_j^2 ; butterfly warp reduction
        float q = fmaf(y0, y0, y1 * y1);
        #pragma unroll
        for (int off = 16; off; off >>= 1)
            q += __shfl_xor_sync(0xffffffffu, q, off);

        if (lane == 0) out[row] = -0.5f * q;
        // loop back with pending: [A']
    }
}

extern "C" void kernel_launch(void* const* d_in, const int* in_sizes, int n_in,
                              void* d_out, int out_size)
{
    const float* Lf = (const float*)d_in[0];   // [B, 2080]
    const float* mu = (const float*)d_in[1];   // [B, 64]
    const float* a  = (const float*)d_in[2];   // [B, 64]
    float* out = (float*)d_out;                // [B, 1]

    const int B = in_sizes[0] / NB_ELEMS;

    // Persistent grid: exactly 6 resident blocks per SM (smem-limited), no
    // oversubscription. Queried at graph-capture time; free at replay.
    int dev = 0, sms = 148;
    cudaGetDevice(&dev);
    cudaDeviceGetAttribute(&sms, cudaDevAttrMultiProcessorCount, dev);
    int blocks = sms * 6;
    const int maxb = (B + WPB - 1) / WPB;
    if (blocks > maxb) blocks = maxb;

    naf_kernel<<<blocks, 32 * WPB>>>(Lf, mu, a, out, B);
}